// round 1
// baseline (speedup 1.0000x reference)
#include <cuda_runtime.h>
#include <math.h>

// ---------------------------------------------------------------------------
// MS-SSIM, 5 levels, img [16,3,512,512] f32. Separable 11-tap Gaussian blur
// (sigma=1.5) computed as two passes in shared memory; 5 blurred fields fused
// into one kernel per level; per-level ssim/cs means accumulated into device
// doubles; final scalar combined on-device.
// ---------------------------------------------------------------------------

#define NPLANES 48            // 16 batch * 3 channels
#define HALO 5
#define TW 32
#define TH 32
#define INW (TW + 10)         // 42
#define INH (TH + 10)         // 42

// Gaussian taps, sigma = 1.5, 11 taps, normalized (computed in double prec).
__device__ __constant__ float kGW_unused[1]; // (keep nothing in cmem path)
#define G0 0.001028380f
#define G1 0.007598758f
#define G2 0.036000770f
#define G3 0.109360700f
#define G4 0.213005550f
#define G5 0.266011740f

__device__ __forceinline__ float gw(int k) {
    // compile-time resolved in fully unrolled loops
    switch (k) {
        case 0: case 10: return G0;
        case 1: case 9:  return G1;
        case 2: case 8:  return G2;
        case 3: case 7:  return G3;
        case 4: case 6:  return G4;
        default:         return G5;
    }
}

#define C1F 0.0001f
#define C2F 0.0009f

// sums[2*level] = sum(ssim_map), sums[2*level+1] = sum(cs_map)
__device__ double g_sums[10];

// pyramid scratch (floats): level1 .. level4 for each image
// offsets: L1=0 (256x256), L2=3145728 (128x128), L3=3932160 (64x64), L4=4128768 (32x32)
#define OFF_L1 0
#define OFF_L2 3145728
#define OFF_L3 3932160
#define OFF_L4 4128768
#define SCR_TOTAL 4177920
__device__ float g_scr1[SCR_TOTAL];
__device__ float g_scr2[SCR_TOTAL];

__global__ void zero_sums_kernel() {
    if (threadIdx.x < 10) g_sums[threadIdx.x] = 0.0;
}

// One block = 32x32 output tile of one (b,c) plane. blockDim = (32,8).
__global__ void __launch_bounds__(256)
ssim_level_kernel(const float* __restrict__ img1, const float* __restrict__ img2,
                  int H, int W, int level)
{
    __shared__ float s1[INH * INW];
    __shared__ float s2[INH * INW];
    __shared__ float h1 [INH * TW];
    __shared__ float h2 [INH * TW];
    __shared__ float h11[INH * TW];
    __shared__ float h22[INH * TW];
    __shared__ float h12[INH * TW];
    __shared__ float red_s[8], red_c[8];

    const int plane = blockIdx.z;
    const int x0 = blockIdx.x * TW;
    const int y0 = blockIdx.y * TH;
    const float* p1 = img1 + (size_t)plane * H * W;
    const float* p2 = img2 + (size_t)plane * H * W;
    const int tx = threadIdx.x, ty = threadIdx.y;
    const int t  = ty * 32 + tx;

    // ---- stage input tile (+halo, zero padded) ----
    #pragma unroll
    for (int idx = t; idx < INH * INW; idx += 256) {
        int r = idx / INW, c = idx - r * INW;
        int gy = y0 + r - HALO;
        int gx = x0 + c - HALO;
        bool ok = (gy >= 0) && (gy < H) && (gx >= 0) && (gx < W);
        float a = 0.f, b = 0.f;
        if (ok) {
            int gi = gy * W + gx;
            a = p1[gi];
            b = p2[gi];
        }
        s1[idx] = a;
        s2[idx] = b;
    }
    __syncthreads();

    // ---- horizontal pass: 5 fields, 42 rows x 32 cols ----
    for (int idx = t; idx < INH * TW; idx += 256) {
        int r = idx / TW, cc = idx - r * TW;
        const float* r1 = s1 + r * INW + cc;
        const float* r2 = s2 + r * INW + cc;
        float a1 = 0.f, a2 = 0.f, a11 = 0.f, a22 = 0.f, a12 = 0.f;
        #pragma unroll
        for (int k = 0; k < 11; k++) {
            float w = gw(k);
            float x = r1[k];
            float y = r2[k];
            float wx = w * x;
            float wy = w * y;
            a1  += wx;
            a2  += wy;
            a11 = fmaf(wx, x, a11);
            a22 = fmaf(wy, y, a22);
            a12 = fmaf(wx, y, a12);
        }
        h1 [idx] = a1;
        h2 [idx] = a2;
        h11[idx] = a11;
        h22[idx] = a22;
        h12[idx] = a12;
    }
    __syncthreads();

    // ---- vertical pass: each thread = column tx, 4 consecutive output rows ----
    float acc[4][5];
    #pragma unroll
    for (int j = 0; j < 4; j++)
        #pragma unroll
        for (int f = 0; f < 5; f++)
            acc[j][f] = 0.f;

    const int rbase = ty * 4;
    #pragma unroll
    for (int k = 0; k < 14; k++) {
        int base = (rbase + k) * TW + tx;
        float v0 = h1 [base];
        float v1 = h2 [base];
        float v2 = h11[base];
        float v3 = h22[base];
        float v4 = h12[base];
        #pragma unroll
        for (int j = 0; j < 4; j++) {
            int ki = k - j;
            if (ki >= 0 && ki <= 10) {
                float w = gw(ki);
                acc[j][0] = fmaf(w, v0, acc[j][0]);
                acc[j][1] = fmaf(w, v1, acc[j][1]);
                acc[j][2] = fmaf(w, v2, acc[j][2]);
                acc[j][3] = fmaf(w, v3, acc[j][3]);
                acc[j][4] = fmaf(w, v4, acc[j][4]);
            }
        }
    }

    // ---- epilogue: ssim / cs maps + local sums ----
    float lssim = 0.f, lcs = 0.f;
    #pragma unroll
    for (int j = 0; j < 4; j++) {
        float mu1 = acc[j][0], mu2 = acc[j][1];
        float m11 = acc[j][2], m22 = acc[j][3], m12 = acc[j][4];
        float mu1sq = mu1 * mu1;
        float mu2sq = mu2 * mu2;
        float mu12  = mu1 * mu2;
        float s1sq  = m11 - mu1sq;
        float s2sq  = m22 - mu2sq;
        float s12   = m12 - mu12;
        float cs    = __fdividef(2.f * s12 + C2F, s1sq + s2sq + C2F);
        float ssim  = __fdividef(2.f * mu12 + C1F, mu1sq + mu2sq + C1F) * cs;
        lssim += ssim;
        lcs   += cs;
    }

    // ---- block reduction ----
    #pragma unroll
    for (int o = 16; o > 0; o >>= 1) {
        lssim += __shfl_xor_sync(0xFFFFFFFFu, lssim, o);
        lcs   += __shfl_xor_sync(0xFFFFFFFFu, lcs,   o);
    }
    if (tx == 0) {
        red_s[ty] = lssim;
        red_c[ty] = lcs;
    }
    __syncthreads();
    if (t == 0) {
        float S = 0.f, Cc = 0.f;
        #pragma unroll
        for (int i = 0; i < 8; i++) { S += red_s[i]; Cc += red_c[i]; }
        atomicAdd(&g_sums[2 * level],     (double)S);
        atomicAdd(&g_sums[2 * level + 1], (double)Cc);
    }
}

// 2x2 average pool, NCHW, exact halving
__global__ void pool2_kernel(const float* __restrict__ in, float* __restrict__ out,
                             int H2, int W2)
{
    int n = NPLANES * H2 * W2;
    int i = blockIdx.x * blockDim.x + threadIdx.x;
    if (i >= n) return;
    int x = i % W2;
    int y = (i / W2) % H2;
    int p = i / (W2 * H2);
    int W = W2 * 2;
    const float* b = in + ((size_t)p * (H2 * 2) + 2 * y) * W + 2 * x;
    out[i] = 0.25f * (b[0] + b[1] + b[W] + b[W + 1]);
}

__global__ void finalize_kernel(float* __restrict__ out)
{
    const double w[5] = {0.0448, 0.2856, 0.3001, 0.2363, 0.1333};
    double res = 1.0;
    #pragma unroll
    for (int l = 0; l < 5; l++) {
        int side = 512 >> l;
        double cnt = (double)NPLANES * side * side;
        double v = (l < 4) ? (g_sums[2 * l + 1] / cnt)   // mcs
                           : (g_sums[2 * l] / cnt);      // mssim at last level
        res *= pow(v, w[l]);
    }
    out[0] = (float)res;
}

extern "C" void kernel_launch(void* const* d_in, const int* in_sizes, int n_in,
                              void* d_out, int out_size)
{
    const float* img1 = (const float*)d_in[0];
    const float* img2 = (const float*)d_in[1];
    // d_in[2] (window) unused: taps are compile-time constants (sigma=1.5 Gaussian)
    float* out = (float*)d_out;

    float *scr1 = nullptr, *scr2 = nullptr;
    cudaGetSymbolAddress((void**)&scr1, g_scr1);
    cudaGetSymbolAddress((void**)&scr2, g_scr2);

    const float* a[5];
    const float* b[5];
    a[0] = img1;            b[0] = img2;
    a[1] = scr1 + OFF_L1;   b[1] = scr2 + OFF_L1;
    a[2] = scr1 + OFF_L2;   b[2] = scr2 + OFF_L2;
    a[3] = scr1 + OFF_L3;   b[3] = scr2 + OFF_L3;
    a[4] = scr1 + OFF_L4;   b[4] = scr2 + OFF_L4;

    zero_sums_kernel<<<1, 32>>>();

    dim3 blk(32, 8);
    for (int l = 0; l < 5; l++) {
        int side = 512 >> l;
        dim3 grd(side / TW, side / TH, NPLANES);
        ssim_level_kernel<<<grd, blk>>>(a[l], b[l], side, side, l);
        if (l < 4) {
            int s2 = side / 2;
            int n = NPLANES * s2 * s2;
            int nb = (n + 255) / 256;
            pool2_kernel<<<nb, 256>>>(a[l], (float*)a[l + 1], s2, s2);
            pool2_kernel<<<nb, 256>>>(b[l], (float*)b[l + 1], s2, s2);
        }
    }
    finalize_kernel<<<1, 1>>>(out);
}

// round 2
// speedup vs baseline: 1.2545x; 1.2545x over previous
#include <cuda_runtime.h>
#include <math.h>

// ---------------------------------------------------------------------------
// MS-SSIM, 5 levels, [16,3,512,512] f32.
// Per level: one fused kernel does separable 11-tap Gaussian blur of the
// 4 fields (u, v, u^2, v^2) where u=x+y, v=x-y, computes ssim/cs sums,
// AND writes the 2x2-pooled next-level images (pool fused, no pool kernels).
// ---------------------------------------------------------------------------

#define NPLANES 48
#define HALO 5
#define TW 32
#define TH 32
#define INW (TW + 10)   // 42
#define INH (TH + 10)   // 42

// Gaussian taps, sigma=1.5, 11 taps, normalized.
#define G0 0.001028380f
#define G1 0.007598758f
#define G2 0.036000770f
#define G3 0.109360700f
#define G4 0.213005550f
#define G5 0.266011740f

__device__ __forceinline__ float gw(int k) {
    switch (k) {
        case 0: case 10: return G0;
        case 1: case 9:  return G1;
        case 2: case 8:  return G2;
        case 3: case 7:  return G3;
        case 4: case 6:  return G4;
        default:         return G5;
    }
}

#define C1F 0.0001f
#define C2F 0.0009f

__device__ double g_sums[10];  // [2l]=ssim sum, [2l+1]=cs sum

// pyramid scratch
#define OFF_L1 0
#define OFF_L2 3145728
#define OFF_L3 3932160
#define OFF_L4 4128768
#define SCR_TOTAL 4177920
__device__ float g_scr1[SCR_TOTAL];
__device__ float g_scr2[SCR_TOTAL];

__global__ void zero_sums_kernel() {
    if (threadIdx.x < 10) g_sums[threadIdx.x] = 0.0;
}

// One block = 32x32 output tile of one plane. blockDim=(32,8)=256.
// All level sides (512..32) divide evenly by 32, so no output guards.
__global__ void __launch_bounds__(256)
ssim_level_kernel(const float* __restrict__ img1, const float* __restrict__ img2,
                  float* __restrict__ pool1, float* __restrict__ pool2,
                  int H, int W, int level)
{
    __shared__ float s_u[INH * INW];
    __shared__ float s_v[INH * INW];
    __shared__ float hU [INH * TW];
    __shared__ float hV [INH * TW];
    __shared__ float hUU[INH * TW];
    __shared__ float hVV[INH * TW];
    __shared__ float red_s[8], red_c[8];

    const int plane = blockIdx.z;
    const int x0 = blockIdx.x * TW;
    const int y0 = blockIdx.y * TH;
    const float* p1 = img1 + (size_t)plane * H * W;
    const float* p2 = img2 + (size_t)plane * H * W;
    const int tx = threadIdx.x, ty = threadIdx.y;
    const int t  = ty * 32 + tx;

    // ---- stage input tile (+halo, zero padded), store u=x+y, v=x-y ----
    for (int idx = t; idx < INH * INW; idx += 256) {
        int r = idx / INW, c = idx - r * INW;
        int gy = y0 + r - HALO;
        int gx = x0 + c - HALO;
        float a = 0.f, b = 0.f;
        if (gy >= 0 && gy < H && gx >= 0 && gx < W) {
            int gi = gy * W + gx;
            a = __ldg(p1 + gi);
            b = __ldg(p2 + gi);
        }
        s_u[idx] = a + b;
        s_v[idx] = a - b;
    }
    __syncthreads();

    // ---- fused 2x2 pool of the 32x32 interior -> 16x16, 1 output/thread ----
    if (pool1) {
        int i = t >> 4;        // 0..15 pooled row
        int j = t & 15;        // 0..15 pooled col
        int base = (HALO + 2 * i) * INW + HALO + 2 * j;
        float u00 = s_u[base],       v00 = s_v[base];
        float u01 = s_u[base + 1],   v01 = s_v[base + 1];
        float u10 = s_u[base + INW], v10 = s_v[base + INW];
        float u11 = s_u[base + INW + 1], v11 = s_v[base + INW + 1];
        float su = (u00 + u01) + (u10 + u11);
        float sv = (v00 + v01) + (v10 + v11);
        int W2 = W >> 1;
        size_t oi = (size_t)plane * (W2 * (H >> 1)) + ((y0 >> 1) + i) * W2 + (x0 >> 1) + j;
        pool1[oi] = 0.125f * (su + sv);
        pool2[oi] = 0.125f * (su - sv);
    }

    // ---- horizontal pass: 4 fields over 42 rows x 32 cols ----
    for (int idx = t; idx < INH * TW; idx += 256) {
        int r = idx >> 5, cc = idx & 31;
        const float* ru = s_u + r * INW + cc;
        const float* rv = s_v + r * INW + cc;
        float aU = 0.f, aV = 0.f, aUU = 0.f, aVV = 0.f;
        #pragma unroll
        for (int k = 0; k < 11; k++) {
            const float w = gw(k);
            float u = ru[k];
            float v = rv[k];
            float uu = u * u;
            float vv = v * v;
            aU  = fmaf(w, u,  aU);   // FFMA-imm (w is a literal)
            aV  = fmaf(w, v,  aV);
            aUU = fmaf(w, uu, aUU);
            aVV = fmaf(w, vv, aVV);
        }
        hU [idx] = aU;
        hV [idx] = aV;
        hUU[idx] = aUU;
        hVV[idx] = aVV;
    }
    __syncthreads();

    // ---- vertical pass: column tx, 4 consecutive output rows per thread ----
    float aU[4], aV[4], aUU[4], aVV[4];
    #pragma unroll
    for (int j = 0; j < 4; j++) { aU[j] = aV[j] = aUU[j] = aVV[j] = 0.f; }

    const int rbase = ty * 4;
    #pragma unroll
    for (int k = 0; k < 14; k++) {
        int base = (rbase + k) * TW + tx;
        float u  = hU [base];
        float v  = hV [base];
        float uu = hUU[base];
        float vv = hVV[base];
        #pragma unroll
        for (int j = 0; j < 4; j++) {
            int ki = k - j;
            if (ki >= 0 && ki <= 10) {
                const float w = gw(ki);
                aU [j] = fmaf(w, u,  aU [j]);
                aV [j] = fmaf(w, v,  aV [j]);
                aUU[j] = fmaf(w, uu, aUU[j]);
                aVV[j] = fmaf(w, vv, aVV[j]);
            }
        }
    }

    // ---- epilogue ----
    // U=mu1+mu2, V=mu1-mu2, P=blur(u^2), Q=blur(v^2)
    // 2*mu1mu2+C1 = (U^2-V^2)/2 + C1 ; mu1^2+mu2^2 = (U^2+V^2)/2
    // sig1+sig2   = (P+Q-U^2-V^2)/2  ; 2*sig12 = (P-Q-U^2+V^2)/2
    float lssim = 0.f, lcs = 0.f;
    #pragma unroll
    for (int j = 0; j < 4; j++) {
        float A = aU[j] * aU[j];
        float B = aV[j] * aV[j];
        float P = aUU[j], Q = aVV[j];
        float num_l = 0.5f * (A - B) + C1F;
        float den_l = 0.5f * (A + B) + C1F;
        float num_c = 0.5f * ((P - Q) - (A - B)) + C2F;
        float den_c = 0.5f * ((P + Q) - (A + B)) + C2F;
        float cs = __fdividef(num_c, den_c);
        lssim += __fdividef(num_l, den_l) * cs;
        lcs   += cs;
    }

    #pragma unroll
    for (int o = 16; o > 0; o >>= 1) {
        lssim += __shfl_xor_sync(0xFFFFFFFFu, lssim, o);
        lcs   += __shfl_xor_sync(0xFFFFFFFFu, lcs,   o);
    }
    if (tx == 0) { red_s[ty] = lssim; red_c[ty] = lcs; }
    __syncthreads();
    if (t == 0) {
        float S = 0.f, Cc = 0.f;
        #pragma unroll
        for (int i = 0; i < 8; i++) { S += red_s[i]; Cc += red_c[i]; }
        atomicAdd(&g_sums[2 * level],     (double)S);
        atomicAdd(&g_sums[2 * level + 1], (double)Cc);
    }
}

__global__ void finalize_kernel(float* __restrict__ out)
{
    const double w[5] = {0.0448, 0.2856, 0.3001, 0.2363, 0.1333};
    double res = 1.0;
    #pragma unroll
    for (int l = 0; l < 5; l++) {
        int side = 512 >> l;
        double cnt = (double)NPLANES * side * side;
        double v = (l < 4) ? (g_sums[2 * l + 1] / cnt)
                           : (g_sums[2 * l] / cnt);
        res *= pow(v, w[l]);
    }
    out[0] = (float)res;
}

extern "C" void kernel_launch(void* const* d_in, const int* in_sizes, int n_in,
                              void* d_out, int out_size)
{
    const float* img1 = (const float*)d_in[0];
    const float* img2 = (const float*)d_in[1];
    float* out = (float*)d_out;

    float *scr1 = nullptr, *scr2 = nullptr;
    cudaGetSymbolAddress((void**)&scr1, g_scr1);
    cudaGetSymbolAddress((void**)&scr2, g_scr2);

    const float* a[5];
    const float* b[5];
    a[0] = img1;            b[0] = img2;
    a[1] = scr1 + OFF_L1;   b[1] = scr2 + OFF_L1;
    a[2] = scr1 + OFF_L2;   b[2] = scr2 + OFF_L2;
    a[3] = scr1 + OFF_L3;   b[3] = scr2 + OFF_L3;
    a[4] = scr1 + OFF_L4;   b[4] = scr2 + OFF_L4;

    zero_sums_kernel<<<1, 32>>>();

    dim3 blk(32, 8);
    for (int l = 0; l < 5; l++) {
        int side = 512 >> l;
        dim3 grd(side / TW, side / TH, NPLANES);
        float* n1 = (l < 4) ? (float*)a[l + 1] : nullptr;
        float* n2 = (l < 4) ? (float*)b[l + 1] : nullptr;
        ssim_level_kernel<<<grd, blk>>>(a[l], b[l], n1, n2, side, side, l);
    }
    finalize_kernel<<<1, 1>>>(out);
}

// round 3
// speedup vs baseline: 1.2688x; 1.0114x over previous
#include <cuda_runtime.h>
#include <math.h>

// ---------------------------------------------------------------------------
// MS-SSIM, 5 levels, [16,3,512,512] f32.
// u=x+y, v=x-y reformulation (4 blurred fields). Separable blur:
//   h-pass: 4 outputs/thread, vectorized LDS.128 window loads, u^2 reuse
//   v-pass: float4-interleaved fields, LDS.128
// 2x2 pool for next level fused into the same kernel.
// ---------------------------------------------------------------------------

#define NPLANES 48
#define HALO 5
#define TW 32
#define TH 32
#define INW 42
#define INWP 44        // padded row stride (16B-aligned groups)
#define INH 42

#define G0 0.001028380f
#define G1 0.007598758f
#define G2 0.036000770f
#define G3 0.109360700f
#define G4 0.213005550f
#define G5 0.266011740f

__device__ __forceinline__ float gw(int k) {
    switch (k) {
        case 0: case 10: return G0;
        case 1: case 9:  return G1;
        case 2: case 8:  return G2;
        case 3: case 7:  return G3;
        case 4: case 6:  return G4;
        default:         return G5;
    }
}

#define C1F 0.0001f
#define C2F 0.0009f

__device__ double g_sums[10];

#define OFF_L1 0
#define OFF_L2 3145728
#define OFF_L3 3932160
#define OFF_L4 4128768
#define SCR_TOTAL 4177920
__device__ float g_scr1[SCR_TOTAL];
__device__ float g_scr2[SCR_TOTAL];

__global__ void zero_sums_kernel() {
    if (threadIdx.x < 10) g_sums[threadIdx.x] = 0.0;
}

// One block = 32x32 output tile. blockDim=(32,8)=256.
__global__ void __launch_bounds__(256)
ssim_level_kernel(const float* __restrict__ img1, const float* __restrict__ img2,
                  float* __restrict__ pool1, float* __restrict__ pool2,
                  int H, int W, int level)
{
    __shared__ __align__(16) float s_u[INH * INWP];
    __shared__ __align__(16) float s_v[INH * INWP];
    __shared__ __align__(16) float4 h4[INH * TW];   // {U,V,UU,VV}
    __shared__ float red_s[8], red_c[8];

    const int plane = blockIdx.z;
    const int x0 = blockIdx.x * TW;
    const int y0 = blockIdx.y * TH;
    const float* p1 = img1 + (size_t)plane * H * W;
    const float* p2 = img2 + (size_t)plane * H * W;
    const int tx = threadIdx.x, ty = threadIdx.y;
    const int t  = ty * 32 + tx;

    // ---- stage (+halo, zero pad), u=a+b, v=a-b, padded row stride ----
    for (int idx = t; idx < INH * INW; idx += 256) {
        int r = idx / INW, c = idx - r * INW;
        int gy = y0 + r - HALO;
        int gx = x0 + c - HALO;
        float a = 0.f, b = 0.f;
        if (gy >= 0 && gy < H && gx >= 0 && gx < W) {
            int gi = gy * W + gx;
            a = __ldg(p1 + gi);
            b = __ldg(p2 + gi);
        }
        s_u[r * INWP + c] = a + b;
        s_v[r * INWP + c] = a - b;
    }
    __syncthreads();

    // ---- fused 2x2 pool of interior -> 16x16 ----
    if (pool1) {
        int i = t >> 4, j = t & 15;
        int base = (HALO + 2 * i) * INWP + HALO + 2 * j;
        float su = (s_u[base] + s_u[base + 1]) + (s_u[base + INWP] + s_u[base + INWP + 1]);
        float sv = (s_v[base] + s_v[base + 1]) + (s_v[base + INWP] + s_v[base + INWP + 1]);
        int W2 = W >> 1;
        size_t oi = (size_t)plane * (W2 * (H >> 1)) + ((y0 >> 1) + i) * W2 + (x0 >> 1) + j;
        pool1[oi] = 0.125f * (su + sv);
        pool2[oi] = 0.125f * (su - sv);
    }

    // ---- horizontal pass: 42 rows x 8 groups of 4 cols = 336 tasks ----
    for (int task = t; task < INH * 8; task += 256) {
        int r  = task >> 3;
        int cc = (task & 7) << 2;
        const float* pu = s_u + r * INWP + cc;
        const float* pv = s_v + r * INWP + cc;

        // 14-float aligned window per field
        float4 a0 = *(const float4*)(pu);
        float4 a1 = *(const float4*)(pu + 4);
        float4 a2 = *(const float4*)(pu + 8);
        float2 a3 = *(const float2*)(pu + 12);
        float u[14] = {a0.x,a0.y,a0.z,a0.w, a1.x,a1.y,a1.z,a1.w,
                       a2.x,a2.y,a2.z,a2.w, a3.x,a3.y};
        float4 b0 = *(const float4*)(pv);
        float4 b1 = *(const float4*)(pv + 4);
        float4 b2 = *(const float4*)(pv + 8);
        float2 b3 = *(const float2*)(pv + 12);
        float v[14] = {b0.x,b0.y,b0.z,b0.w, b1.x,b1.y,b1.z,b1.w,
                       b2.x,b2.y,b2.z,b2.w, b3.x,b3.y};

        float uu[14], vv[14];
        #pragma unroll
        for (int i = 0; i < 14; i++) { uu[i] = u[i] * u[i]; vv[i] = v[i] * v[i]; }

        #pragma unroll
        for (int j = 0; j < 4; j++) {
            float U = 0.f, V = 0.f, P = 0.f, Q = 0.f;
            #pragma unroll
            for (int k = 0; k < 11; k++) {
                const float w = gw(k);
                U = fmaf(w, u [j + k], U);
                V = fmaf(w, v [j + k], V);
                P = fmaf(w, uu[j + k], P);
                Q = fmaf(w, vv[j + k], Q);
            }
            h4[r * TW + cc + j] = make_float4(U, V, P, Q);
        }
    }
    __syncthreads();

    // ---- vertical pass: column tx, 4 output rows/thread, LDS.128 ----
    float aU[4] = {0,0,0,0}, aV[4] = {0,0,0,0}, aP[4] = {0,0,0,0}, aQ[4] = {0,0,0,0};
    const int rbase = ty * 4;
    #pragma unroll
    for (int k = 0; k < 14; k++) {
        float4 hv = h4[(rbase + k) * TW + tx];
        #pragma unroll
        for (int j = 0; j < 4; j++) {
            int ki = k - j;
            if (ki >= 0 && ki <= 10) {
                const float w = gw(ki);
                aU[j] = fmaf(w, hv.x, aU[j]);
                aV[j] = fmaf(w, hv.y, aV[j]);
                aP[j] = fmaf(w, hv.z, aP[j]);
                aQ[j] = fmaf(w, hv.w, aQ[j]);
            }
        }
    }

    // ---- epilogue ----
    float lssim = 0.f, lcs = 0.f;
    #pragma unroll
    for (int j = 0; j < 4; j++) {
        float A = aU[j] * aU[j];
        float B = aV[j] * aV[j];
        float P = aP[j], Q = aQ[j];
        float num_l = 0.5f * (A - B) + C1F;
        float den_l = 0.5f * (A + B) + C1F;
        float num_c = 0.5f * ((P - Q) - (A - B)) + C2F;
        float den_c = 0.5f * ((P + Q) - (A + B)) + C2F;
        float cs = __fdividef(num_c, den_c);
        lssim += __fdividef(num_l, den_l) * cs;
        lcs   += cs;
    }

    #pragma unroll
    for (int o = 16; o > 0; o >>= 1) {
        lssim += __shfl_xor_sync(0xFFFFFFFFu, lssim, o);
        lcs   += __shfl_xor_sync(0xFFFFFFFFu, lcs,   o);
    }
    if (tx == 0) { red_s[ty] = lssim; red_c[ty] = lcs; }
    __syncthreads();
    if (t == 0) {
        float S = 0.f, Cc = 0.f;
        #pragma unroll
        for (int i = 0; i < 8; i++) { S += red_s[i]; Cc += red_c[i]; }
        atomicAdd(&g_sums[2 * level],     (double)S);
        atomicAdd(&g_sums[2 * level + 1], (double)Cc);
    }
}

__global__ void finalize_kernel(float* __restrict__ out)
{
    const double w[5] = {0.0448, 0.2856, 0.3001, 0.2363, 0.1333};
    double res = 1.0;
    #pragma unroll
    for (int l = 0; l < 5; l++) {
        int side = 512 >> l;
        double cnt = (double)NPLANES * side * side;
        double v = (l < 4) ? (g_sums[2 * l + 1] / cnt)
                           : (g_sums[2 * l] / cnt);
        res *= pow(v, w[l]);
    }
    out[0] = (float)res;
}

extern "C" void kernel_launch(void* const* d_in, const int* in_sizes, int n_in,
                              void* d_out, int out_size)
{
    const float* img1 = (const float*)d_in[0];
    const float* img2 = (const float*)d_in[1];
    float* out = (float*)d_out;

    float *scr1 = nullptr, *scr2 = nullptr;
    cudaGetSymbolAddress((void**)&scr1, g_scr1);
    cudaGetSymbolAddress((void**)&scr2, g_scr2);

    const float* a[5];
    const float* b[5];
    a[0] = img1;            b[0] = img2;
    a[1] = scr1 + OFF_L1;   b[1] = scr2 + OFF_L1;
    a[2] = scr1 + OFF_L2;   b[2] = scr2 + OFF_L2;
    a[3] = scr1 + OFF_L3;   b[3] = scr2 + OFF_L3;
    a[4] = scr1 + OFF_L4;   b[4] = scr2 + OFF_L4;

    zero_sums_kernel<<<1, 32>>>();

    dim3 blk(32, 8);
    for (int l = 0; l < 5; l++) {
        int side = 512 >> l;
        dim3 grd(side / TW, side / TH, NPLANES);
        float* n1 = (l < 4) ? (float*)a[l + 1] : nullptr;
        float* n2 = (l < 4) ? (float*)b[l + 1] : nullptr;
        ssim_level_kernel<<<grd, blk>>>(a[l], b[l], n1, n2, side, side, l);
    }
    finalize_kernel<<<1, 1>>>(out);
}

// round 4
// speedup vs baseline: 1.2795x; 1.0084x over previous
#include <cuda_runtime.h>
#include <math.h>

// ---------------------------------------------------------------------------
// MS-SSIM, 5 levels, [16,3,512,512] f32.
// u=x+y, v=x-y reformulation (4 blurred fields). Separable blur:
//   h-pass: 4 outputs/thread, vectorized LDS.128 window loads, u^2 reuse
//   v-pass: float4-interleaved fields, 14 prefetched LDS.128 then FMA chain
// __launch_bounds__(256,2) raises reg budget to avoid the R3 spills.
// 2x2 pool for next level fused into the same kernel.
// ---------------------------------------------------------------------------

#define NPLANES 48
#define HALO 5
#define TW 32
#define TH 32
#define INW 42
#define INWP 44        // padded row stride (16B-aligned groups)
#define INH 42

#define G0 0.001028380f
#define G1 0.007598758f
#define G2 0.036000770f
#define G3 0.109360700f
#define G4 0.213005550f
#define G5 0.266011740f

__device__ __forceinline__ float gw(int k) {
    switch (k) {
        case 0: case 10: return G0;
        case 1: case 9:  return G1;
        case 2: case 8:  return G2;
        case 3: case 7:  return G3;
        case 4: case 6:  return G4;
        default:         return G5;
    }
}

#define C1F 0.0001f
#define C2F 0.0009f

__device__ double g_sums[10];

#define OFF_L1 0
#define OFF_L2 3145728
#define OFF_L3 3932160
#define OFF_L4 4128768
#define SCR_TOTAL 4177920
__device__ float g_scr1[SCR_TOTAL];
__device__ float g_scr2[SCR_TOTAL];

__global__ void zero_sums_kernel() {
    if (threadIdx.x < 10) g_sums[threadIdx.x] = 0.0;
}

// One block = 32x32 output tile. blockDim=(32,8)=256. Reg budget: 128/thread.
__global__ void __launch_bounds__(256, 2)
ssim_level_kernel(const float* __restrict__ img1, const float* __restrict__ img2,
                  float* __restrict__ pool1, float* __restrict__ pool2,
                  int H, int W, int level)
{
    __shared__ __align__(16) float s_u[INH * INWP];
    __shared__ __align__(16) float s_v[INH * INWP];
    __shared__ __align__(16) float4 h4[INH * TW];   // {U,V,UU,VV}
    __shared__ float red_s[8], red_c[8];

    const int plane = blockIdx.z;
    const int x0 = blockIdx.x * TW;
    const int y0 = blockIdx.y * TH;
    const float* p1 = img1 + (size_t)plane * H * W;
    const float* p2 = img2 + (size_t)plane * H * W;
    const int tx = threadIdx.x, ty = threadIdx.y;
    const int t  = ty * 32 + tx;

    // ---- stage (+halo, zero pad), u=a+b, v=a-b, padded row stride ----
    for (int idx = t; idx < INH * INW; idx += 256) {
        int r = idx / INW, c = idx - r * INW;
        int gy = y0 + r - HALO;
        int gx = x0 + c - HALO;
        float a = 0.f, b = 0.f;
        if (gy >= 0 && gy < H && gx >= 0 && gx < W) {
            int gi = gy * W + gx;
            a = __ldg(p1 + gi);
            b = __ldg(p2 + gi);
        }
        s_u[r * INWP + c] = a + b;
        s_v[r * INWP + c] = a - b;
    }
    __syncthreads();

    // ---- fused 2x2 pool of interior -> 16x16 ----
    if (pool1) {
        int i = t >> 4, j = t & 15;
        int base = (HALO + 2 * i) * INWP + HALO + 2 * j;
        float su = (s_u[base] + s_u[base + 1]) + (s_u[base + INWP] + s_u[base + INWP + 1]);
        float sv = (s_v[base] + s_v[base + 1]) + (s_v[base + INWP] + s_v[base + INWP + 1]);
        int W2 = W >> 1;
        size_t oi = (size_t)plane * (W2 * (H >> 1)) + ((y0 >> 1) + i) * W2 + (x0 >> 1) + j;
        pool1[oi] = 0.125f * (su + sv);
        pool2[oi] = 0.125f * (su - sv);
    }

    // ---- horizontal pass: 42 rows x 8 groups of 4 cols = 336 tasks ----
    for (int task = t; task < INH * 8; task += 256) {
        int r  = task >> 3;
        int cc = (task & 7) << 2;
        const float* pu = s_u + r * INWP + cc;
        const float* pv = s_v + r * INWP + cc;

        // 14-float aligned window per field (registers; budget raised so no spill)
        float4 a0 = *(const float4*)(pu);
        float4 a1 = *(const float4*)(pu + 4);
        float4 a2 = *(const float4*)(pu + 8);
        float2 a3 = *(const float2*)(pu + 12);
        float u[14] = {a0.x,a0.y,a0.z,a0.w, a1.x,a1.y,a1.z,a1.w,
                       a2.x,a2.y,a2.z,a2.w, a3.x,a3.y};
        float4 b0 = *(const float4*)(pv);
        float4 b1 = *(const float4*)(pv + 4);
        float4 b2 = *(const float4*)(pv + 8);
        float2 b3 = *(const float2*)(pv + 12);
        float v[14] = {b0.x,b0.y,b0.z,b0.w, b1.x,b1.y,b1.z,b1.w,
                       b2.x,b2.y,b2.z,b2.w, b3.x,b3.y};

        float uu[14], vv[14];
        #pragma unroll
        for (int i = 0; i < 14; i++) { uu[i] = u[i] * u[i]; vv[i] = v[i] * v[i]; }

        #pragma unroll
        for (int j = 0; j < 4; j++) {
            float U = 0.f, V = 0.f, P = 0.f, Q = 0.f;
            #pragma unroll
            for (int k = 0; k < 11; k++) {
                const float w = gw(k);
                U = fmaf(w, u [j + k], U);
                V = fmaf(w, v [j + k], V);
                P = fmaf(w, uu[j + k], P);
                Q = fmaf(w, vv[j + k], Q);
            }
            h4[r * TW + cc + j] = make_float4(U, V, P, Q);
        }
    }
    __syncthreads();

    // ---- vertical pass: column tx, 4 output rows/thread ----
    // Prefetch all 14 float4 rows first (MLP), then run the FMA chain.
    const int rbase = ty * 4;
    float4 hv[14];
    #pragma unroll
    for (int k = 0; k < 14; k++)
        hv[k] = h4[(rbase + k) * TW + tx];

    float aU[4] = {0,0,0,0}, aV[4] = {0,0,0,0}, aP[4] = {0,0,0,0}, aQ[4] = {0,0,0,0};
    #pragma unroll
    for (int k = 0; k < 14; k++) {
        #pragma unroll
        for (int j = 0; j < 4; j++) {
            int ki = k - j;
            if (ki >= 0 && ki <= 10) {
                const float w = gw(ki);
                aU[j] = fmaf(w, hv[k].x, aU[j]);
                aV[j] = fmaf(w, hv[k].y, aV[j]);
                aP[j] = fmaf(w, hv[k].z, aP[j]);
                aQ[j] = fmaf(w, hv[k].w, aQ[j]);
            }
        }
    }

    // ---- epilogue ----
    float lssim = 0.f, lcs = 0.f;
    #pragma unroll
    for (int j = 0; j < 4; j++) {
        float A = aU[j] * aU[j];
        float B = aV[j] * aV[j];
        float P = aP[j], Q = aQ[j];
        float num_l = 0.5f * (A - B) + C1F;
        float den_l = 0.5f * (A + B) + C1F;
        float num_c = 0.5f * ((P - Q) - (A - B)) + C2F;
        float den_c = 0.5f * ((P + Q) - (A + B)) + C2F;
        float cs = __fdividef(num_c, den_c);
        lssim += __fdividef(num_l, den_l) * cs;
        lcs   += cs;
    }

    #pragma unroll
    for (int o = 16; o > 0; o >>= 1) {
        lssim += __shfl_xor_sync(0xFFFFFFFFu, lssim, o);
        lcs   += __shfl_xor_sync(0xFFFFFFFFu, lcs,   o);
    }
    if (tx == 0) { red_s[ty] = lssim; red_c[ty] = lcs; }
    __syncthreads();
    if (t == 0) {
        float S = 0.f, Cc = 0.f;
        #pragma unroll
        for (int i = 0; i < 8; i++) { S += red_s[i]; Cc += red_c[i]; }
        atomicAdd(&g_sums[2 * level],     (double)S);
        atomicAdd(&g_sums[2 * level + 1], (double)Cc);
    }
}

__global__ void finalize_kernel(float* __restrict__ out)
{
    const double w[5] = {0.0448, 0.2856, 0.3001, 0.2363, 0.1333};
    double res = 1.0;
    #pragma unroll
    for (int l = 0; l < 5; l++) {
        int side = 512 >> l;
        double cnt = (double)NPLANES * side * side;
        double v = (l < 4) ? (g_sums[2 * l + 1] / cnt)
                           : (g_sums[2 * l] / cnt);
        res *= pow(v, w[l]);
    }
    out[0] = (float)res;
}

extern "C" void kernel_launch(void* const* d_in, const int* in_sizes, int n_in,
                              void* d_out, int out_size)
{
    const float* img1 = (const float*)d_in[0];
    const float* img2 = (const float*)d_in[1];
    float* out = (float*)d_out;

    float *scr1 = nullptr, *scr2 = nullptr;
    cudaGetSymbolAddress((void**)&scr1, g_scr1);
    cudaGetSymbolAddress((void**)&scr2, g_scr2);

    const float* a[5];
    const float* b[5];
    a[0] = img1;            b[0] = img2;
    a[1] = scr1 + OFF_L1;   b[1] = scr2 + OFF_L1;
    a[2] = scr1 + OFF_L2;   b[2] = scr2 + OFF_L2;
    a[3] = scr1 + OFF_L3;   b[3] = scr2 + OFF_L3;
    a[4] = scr1 + OFF_L4;   b[4] = scr2 + OFF_L4;

    zero_sums_kernel<<<1, 32>>>();

    dim3 blk(32, 8);
    for (int l = 0; l < 5; l++) {
        int side = 512 >> l;
        dim3 grd(side / TW, side / TH, NPLANES);
        float* n1 = (l < 4) ? (float*)a[l + 1] : nullptr;
        float* n2 = (l < 4) ? (float*)b[l + 1] : nullptr;
        ssim_level_kernel<<<grd, blk>>>(a[l], b[l], n1, n2, side, side, l);
    }
    finalize_kernel<<<1, 1>>>(out);
}